// round 3
// baseline (speedup 1.0000x reference)
#include <cuda_runtime.h>
#include <math_constants.h>

// Erosion2d: 3x3 min-pool, stride 1, +1e9 pad == +INF identity.
// x: [16,64,256,256] f32 -> out same shape.
//
// One warp covers full W=256 of R=8 consecutive rows (lane l: cols [8l,8l+7]).
// Register sliding window of 3 input rows + 1-row prefetch double buffer so a
// DRAM load is always in flight during the fmin/shuffle chain.
// Horizontal halo via warp shuffle of the vertical-min vector (no scalar loads).

#define H 256
#define W4 64          // row width in float4 units
#define R 8            // output rows per warp
#define TILES (H / R)  // 32 row-tiles per plane
#define NIMG 1024      // 16*64 planes

__device__ __forceinline__ float min3f(float a, float b, float c) {
    return fminf(fminf(a, b), c);
}
__device__ __forceinline__ float4 min3v(const float4& a, const float4& b, const float4& c) {
    return make_float4(min3f(a.x, b.x, c.x), min3f(a.y, b.y, c.y),
                       min3f(a.z, b.z, c.z), min3f(a.w, b.w, c.w));
}

__global__ void __launch_bounds__(256, 6)
erosion3x3_r8_kernel(const float4* __restrict__ x, float4* __restrict__ out) {
    const int gwarp = (blockIdx.x * blockDim.x + threadIdx.x) >> 5;
    const int lane  = threadIdx.x & 31;

    const int tile = gwarp & (TILES - 1);
    const int img  = gwarp >> 5;          // gwarp / TILES (TILES == 32)
    const int row0 = tile * R;

    // base (float4 units): img*H*W4 + row0*W4 + lane*2
    const size_t base = ((size_t)img << 14) + ((size_t)row0 << 6) + ((size_t)lane << 1);
    const float4* p = x + base;
    float4* po = out + base;

    const float4 INF4 = make_float4(CUDART_INF_F, CUDART_INF_F, CUDART_INF_F, CUDART_INF_F);

    float4 w[3][2];   // sliding window: rows i-1, i, i+1
    float4 pf0, pf1;  // prefetch buffer for row i+1 of next iteration

    // preload: row row0-1 (halo), row row0, prefetch row row0+1
    if (row0 > 0) { w[0][0] = p[-W4]; w[0][1] = p[-W4 + 1]; }
    else          { w[0][0] = INF4;   w[0][1] = INF4; }
    w[1][0] = p[0]; w[1][1] = p[1];
    pf0 = p[W4]; pf1 = p[W4 + 1];    // row0+1 <= 249 < H always

    #pragma unroll
    for (int i = 0; i < R; i++) {
        const int s0 = i % 3, s1 = (i + 1) % 3, s2 = (i + 2) % 3;

        // consume prefetch into window slot
        w[s2][0] = pf0; w[s2][1] = pf1;

        // issue next prefetch (row row0+i+2) BEFORE the compute chain
        if (i < R - 1) {
            const int rr = row0 + i + 2;
            if (rr < H) {
                const float4* q = p + (size_t)(i + 2) * W4;
                pf0 = q[0]; pf1 = q[1];
            } else {
                pf0 = INF4; pf1 = INF4;
            }
        }

        // vertical min over the 3 window rows
        float4 v0 = min3v(w[s0][0], w[s1][0], w[s2][0]);
        float4 v1 = min3v(w[s0][1], w[s1][1], w[s2][1]);

        // horizontal halos via shuffle of the vertical-min vector
        float l = __shfl_up_sync(0xffffffffu, v1.w, 1);    // left nbr's col 8l-1
        float r = __shfl_down_sync(0xffffffffu, v0.x, 1);  // right nbr's col 8l+8
        if (lane == 0)  l = CUDART_INF_F;
        if (lane == 31) r = CUDART_INF_F;

        float4 o0, o1;
        o0.x = min3f(l,    v0.x, v0.y);
        o0.y = min3f(v0.x, v0.y, v0.z);
        o0.z = min3f(v0.y, v0.z, v0.w);
        o0.w = min3f(v0.z, v0.w, v1.x);
        o1.x = min3f(v0.w, v1.x, v1.y);
        o1.y = min3f(v1.x, v1.y, v1.z);
        o1.z = min3f(v1.y, v1.z, v1.w);
        o1.w = min3f(v1.z, v1.w, r);

        float4* qo = po + (size_t)i * W4;
        qo[0] = o0; qo[1] = o1;
    }
}

extern "C" void kernel_launch(void* const* d_in, const int* in_sizes, int n_in,
                              void* d_out, int out_size) {
    const float4* x = (const float4*)d_in[0];
    float4* out = (float4*)d_out;
    // warps = NIMG * TILES = 1024*32 = 32768 -> 4096 blocks of 256 threads
    const int threads = 256;
    const int blocks  = (NIMG * TILES * 32) / threads;
    erosion3x3_r8_kernel<<<blocks, threads>>>(x, out);
}

// round 4
// speedup vs baseline: 1.1486x; 1.1486x over previous
#include <cuda_runtime.h>
#include <math_constants.h>

// Erosion2d: 3x3 min-pool, stride 1, +1e9 pad == +INF identity.
// x: [16,64,256,256] f32 -> out same shape.
//
// One warp covers full W=256 of R=4 consecutive rows (lane l: cols [8l,8l+7]).
// ALL 6 input rows (R+2) are loaded up-front as 12 independent float4 loads
// (MLP=12, fully front-batched) before the fmin/shuffle chain.
// Horizontal halo via warp shuffle of the vertical-min vector (no scalar loads).

#define H 256
#define W4 64          // row width in float4 units
#define R 4            // output rows per warp
#define TILES (H / R)  // 64 row-tiles per plane
#define NIMG 1024      // 16*64 planes

__device__ __forceinline__ float min3f(float a, float b, float c) {
    return fminf(fminf(a, b), c);
}
__device__ __forceinline__ float4 min3v(const float4& a, const float4& b, const float4& c) {
    return make_float4(min3f(a.x, b.x, c.x), min3f(a.y, b.y, c.y),
                       min3f(a.z, b.z, c.z), min3f(a.w, b.w, c.w));
}

__global__ void __launch_bounds__(256, 4)
erosion3x3_batch_kernel(const float4* __restrict__ x, float4* __restrict__ out) {
    const int gwarp = (blockIdx.x * blockDim.x + threadIdx.x) >> 5;
    const int lane  = threadIdx.x & 31;

    const int tile = gwarp & (TILES - 1);
    const int img  = gwarp >> 6;          // gwarp / TILES (TILES == 64)
    const int row0 = tile * R;

    // base (float4 units): img*H*W4 + row0*W4 + lane*2
    const size_t base = ((size_t)img << 14) + ((size_t)row0 << 6) + ((size_t)lane << 1);
    const float4* p = x + base;
    float4* po = out + base;

    const float4 INF4 = make_float4(CUDART_INF_F, CUDART_INF_F, CUDART_INF_F, CUDART_INF_F);

    // Front-batched loads: rows row0-1 .. row0+4  (6 rows x 2 float4 = 12 LDG.128)
    float4 w[6][2];
    const bool top = (row0 == 0);
    const bool bot = (row0 + R == H);

    // Interior rows first (always valid), issued back-to-back:
    w[1][0] = p[0 * W4];     w[1][1] = p[0 * W4 + 1];
    w[2][0] = p[1 * W4];     w[2][1] = p[1 * W4 + 1];
    w[3][0] = p[2 * W4];     w[3][1] = p[2 * W4 + 1];
    w[4][0] = p[3 * W4];     w[4][1] = p[3 * W4 + 1];
    if (!top) { w[0][0] = p[-W4];    w[0][1] = p[-W4 + 1]; }
    else      { w[0][0] = INF4;      w[0][1] = INF4; }
    if (!bot) { w[5][0] = p[4 * W4]; w[5][1] = p[4 * W4 + 1]; }
    else      { w[5][0] = INF4;      w[5][1] = INF4; }

    #pragma unroll
    for (int i = 0; i < R; i++) {
        // vertical min over rows i, i+1, i+2 of the 6-row window
        float4 v0 = min3v(w[i][0], w[i + 1][0], w[i + 2][0]);
        float4 v1 = min3v(w[i][1], w[i + 1][1], w[i + 2][1]);

        // horizontal halos via shuffle of the vertical-min vector
        float l = __shfl_up_sync(0xffffffffu, v1.w, 1);    // left nbr's col 8l-1
        float r = __shfl_down_sync(0xffffffffu, v0.x, 1);  // right nbr's col 8l+8
        if (lane == 0)  l = CUDART_INF_F;
        if (lane == 31) r = CUDART_INF_F;

        float4 o0, o1;
        o0.x = min3f(l,    v0.x, v0.y);
        o0.y = min3f(v0.x, v0.y, v0.z);
        o0.z = min3f(v0.y, v0.z, v0.w);
        o0.w = min3f(v0.z, v0.w, v1.x);
        o1.x = min3f(v0.w, v1.x, v1.y);
        o1.y = min3f(v1.x, v1.y, v1.z);
        o1.z = min3f(v1.y, v1.z, v1.w);
        o1.w = min3f(v1.z, v1.w, r);

        float4* qo = po + (size_t)i * W4;
        qo[0] = o0; qo[1] = o1;
    }
}

extern "C" void kernel_launch(void* const* d_in, const int* in_sizes, int n_in,
                              void* d_out, int out_size) {
    const float4* x = (const float4*)d_in[0];
    float4* out = (float4*)d_out;
    // warps = NIMG * TILES = 1024*64 = 65536 -> 8192 blocks of 256 threads
    const int threads = 256;
    const int blocks  = (NIMG * TILES * 32) / threads;
    erosion3x3_batch_kernel<<<blocks, threads>>>(x, out);
}